// round 11
// baseline (speedup 1.0000x reference)
#include <cuda_runtime.h>
#include <cuda_fp16.h>
#include <cstdint>
#include <math.h>

#define D_MODEL 2048
#define NHEADS 16
#define DK 128
#define MAX_S 2048
#define MAX_M 4096
#define W_ELEMS ((size_t)D_MODEL * D_MODEL)

// ---------------- scratch (static device globals; no allocation) ----------------
__device__ __half g_Wt[4 * W_ELEMS];                 // [4][f][d] transposed fp16 weights (q,k,v,o)
__device__ __half g_xh[(size_t)MAX_M * D_MODEL];     // fp16 copy of x
__device__ __half g_Qh[(size_t)MAX_M * D_MODEL];     // [B,H,S,DK] (scale folded)
__device__ __half g_Kh[(size_t)MAX_M * D_MODEL];
__device__ __half g_Vh[(size_t)MAX_M * D_MODEL];
__device__ __half g_attnH[(size_t)MAX_M * D_MODEL];  // [M, D_MODEL]
__device__ float g_cosT[MAX_S * (DK / 2)];
__device__ float g_sinT[MAX_S * (DK / 2)];

// ---------------- asm helpers ----------------
__device__ __forceinline__ void ldsm4(uint32_t* r, uint32_t addr) {
    asm volatile("ldmatrix.sync.aligned.m8n8.x4.shared.b16 {%0,%1,%2,%3}, [%4];"
                 : "=r"(r[0]), "=r"(r[1]), "=r"(r[2]), "=r"(r[3]) : "r"(addr));
}
__device__ __forceinline__ void ldsm4t(uint32_t* r, uint32_t addr) {
    asm volatile("ldmatrix.sync.aligned.m8n8.x4.trans.shared.b16 {%0,%1,%2,%3}, [%4];"
                 : "=r"(r[0]), "=r"(r[1]), "=r"(r[2]), "=r"(r[3]) : "r"(addr));
}
__device__ __forceinline__ void mma16816(float* d, const uint32_t* a, uint32_t b0, uint32_t b1) {
    asm volatile(
        "mma.sync.aligned.m16n8k16.row.col.f32.f16.f16.f32 "
        "{%0,%1,%2,%3}, {%4,%5,%6,%7}, {%8,%9}, {%0,%1,%2,%3};"
        : "+f"(d[0]), "+f"(d[1]), "+f"(d[2]), "+f"(d[3])
        : "r"(a[0]), "r"(a[1]), "r"(a[2]), "r"(a[3]), "r"(b0), "r"(b1));
}
__device__ __forceinline__ void cp16(uint32_t saddr, const void* gptr) {
    asm volatile("cp.async.cg.shared.global [%0], [%1], 16;" :: "r"(saddr), "l"(gptr));
}
__device__ __forceinline__ void cp_commit() { asm volatile("cp.async.commit_group;"); }
#define CP_WAIT(N) asm volatile("cp.async.wait_group %0;" :: "n"(N))
__device__ __forceinline__ uint32_t packh2(float a, float b) {
    __half2 h = __floats2half2_rn(a, b);
    return *reinterpret_cast<uint32_t*>(&h);
}

// ---------------- RoPE table ----------------
__global__ void rope_table_kernel(const int* __restrict__ pos, int S) {
    int idx = blockIdx.x * blockDim.x + threadIdx.x;
    if (idx >= S * (DK / 2)) return;
    int s = idx / (DK / 2);
    int i = idx % (DK / 2);
    float invf = (float)pow(10000.0, -(double)(2 * i) / (double)DK);
    float ang = (float)pos[s] * invf;
    g_cosT[idx] = cosf(ang);
    g_sinT[idx] = sinf(ang);
}

// ---------------- converters ----------------
__global__ void convert_x_kernel(const float* __restrict__ x, int n) {
    int i = (blockIdx.x * blockDim.x + threadIdx.x) * 4;
    if (i >= n) return;
    float4 v = *reinterpret_cast<const float4*>(x + i);
    uint2 u = {packh2(v.x, v.y), packh2(v.z, v.w)};
    *reinterpret_cast<uint2*>(&g_xh[i]) = u;
}

__global__ void transpose_w_kernel(const float* __restrict__ Wq, const float* __restrict__ Wk,
                                   const float* __restrict__ Wv, const float* __restrict__ Wo) {
    __shared__ float t[32][33];
    const int z = blockIdx.z;
    const float* W = (z == 0) ? Wq : (z == 1) ? Wk : (z == 2) ? Wv : Wo;
    __half* dst = g_Wt + (size_t)z * W_ELEMS;
    int x0 = blockIdx.x * 32, y0 = blockIdx.y * 32;
    int tx = threadIdx.x, ty = threadIdx.y;
#pragma unroll
    for (int i = 0; i < 4; i++)
        t[ty + i * 8][tx] = W[(size_t)(y0 + ty + i * 8) * D_MODEL + x0 + tx];
    __syncthreads();
#pragma unroll
    for (int i = 0; i < 4; i++)
        dst[(size_t)(x0 + ty + i * 8) * D_MODEL + y0 + tx] = __float2half(t[tx][ty + i * 8]);
}

// ---------------- GEMM: 128x128 CTA tile, fp16 mma, 3-stage cp.async ----------------
#define SA 72                       // halves per smem row (64 data + 8 pad); 144B stride
#define G_STAGE_B (128 * SA * 2)    // bytes per matrix per stage (18432)
#define G_SMEM (3 * 2 * G_STAGE_B)  // 110592

__global__ __launch_bounds__(256, 2) void gemm_f16_kernel(float* __restrict__ outF, int M,
                                                          int S, int mode_in) {
    extern __shared__ __align__(16) unsigned char smraw[];
    uint32_t sm = (uint32_t)__cvta_generic_to_shared(smraw);

    const int mode = (mode_in < 0) ? (int)blockIdx.z : mode_in;
    const __half* Ag = (mode_in < 0) ? g_xh : g_attnH;
    const __half* Bg = g_Wt + (size_t)mode * W_ELEMS;  // [n][k] fp16
    const int bm = blockIdx.y * 128;
    const int bn = blockIdx.x * 128;
    const int tid = threadIdx.x;
    const int lane = tid & 31, wid = tid >> 5;
    const int wm = wid & 3, wn = wid >> 2;
    const int lr = lane >> 2, lc = lane & 3;

    const int a_row = (lane & 7) + ((lane >> 3) & 1) * 8;
    const int a_ch = (lane >> 4) * 8;
    const int aoff0 = ((wm * 32 + a_row) * SA + a_ch) * 2;
    const int aoff1 = ((wm * 32 + 16 + a_row) * SA + a_ch) * 2;
    const int b_row = (lane >> 4) * 8 + (lane & 7);
    const int b_k = ((lane >> 3) & 1) * 8;
    const int boff = ((wn * 64 + b_row) * SA + b_k) * 2;

    float acc[2][8][4];
#pragma unroll
    for (int i = 0; i < 2; i++)
#pragma unroll
        for (int j = 0; j < 8; j++)
#pragma unroll
            for (int k = 0; k < 4; k++) acc[i][j][k] = 0.f;

    auto prefetch = [&](int stage, int kt) {
        uint32_t aB = sm + stage * 2 * G_STAGE_B;
        uint32_t bB = aB + G_STAGE_B;
        const __half* Ap = Ag + (size_t)bm * D_MODEL + kt * 64;
        const __half* Bp = Bg + (size_t)bn * D_MODEL + kt * 64;
#pragma unroll
        for (int i = 0; i < 4; i++) {
            int idx = tid + i * 256;
            int r = idx >> 3, c = (idx & 7) * 8;
            cp16(aB + (r * SA + c) * 2, Ap + (size_t)r * D_MODEL + c);
            cp16(bB + (r * SA + c) * 2, Bp + (size_t)r * D_MODEL + c);
        }
    };

    prefetch(0, 0);
    cp_commit();
    prefetch(1, 1);
    cp_commit();

    for (int kt = 0; kt < 32; kt++) {
        CP_WAIT(1);
        __syncthreads();
        if (kt + 2 < 32) prefetch((kt + 2) % 3, kt + 2);
        cp_commit();

        uint32_t aB = sm + (kt % 3) * 2 * G_STAGE_B;
        uint32_t bB = aB + G_STAGE_B;

        uint32_t aF[4][2][4];
#pragma unroll
        for (int kk = 0; kk < 4; kk++) {
            ldsm4(aF[kk][0], aB + aoff0 + kk * 32);
            ldsm4(aF[kk][1], aB + aoff1 + kk * 32);
        }
#pragma unroll
        for (int kk = 0; kk < 4; kk++) {
#pragma unroll
            for (int bt = 0; bt < 4; bt++) {
                uint32_t b[4];
                ldsm4(b, bB + boff + bt * 16 * SA * 2 + kk * 32);
                mma16816(acc[0][2 * bt], aF[kk][0], b[0], b[1]);
                mma16816(acc[1][2 * bt], aF[kk][1], b[0], b[1]);
                mma16816(acc[0][2 * bt + 1], aF[kk][0], b[2], b[3]);
                mma16816(acc[1][2 * bt + 1], aF[kk][1], b[2], b[3]);
            }
        }
    }

#pragma unroll
    for (int mt = 0; mt < 2; mt++) {
#pragma unroll
        for (int nt = 0; nt < 8; nt++) {
#pragma unroll
            for (int half = 0; half < 2; half++) {
                int m = bm + wm * 32 + mt * 16 + lr + half * 8;
                int f = bn + wn * 64 + nt * 8 + lc * 2;
                float c0 = acc[mt][nt][half * 2];
                float c1 = acc[mt][nt][half * 2 + 1];
                if (mode == 3) {
                    *reinterpret_cast<float2*>(outF + (size_t)m * D_MODEL + f) =
                        make_float2(c0, c1);
                } else {
                    int b = m / S, s = m - b * S;
                    int h = f >> 7, d = f & (DK - 1);
                    float o0 = c0, o1 = c1;
                    if (mode < 2) {
                        int i = d >> 1;
                        float cs = g_cosT[s * (DK / 2) + i];
                        float sn = g_sinT[s * (DK / 2) + i];
                        o0 = c0 * cs - c1 * sn;
                        o1 = c0 * sn + c1 * cs;
                        if (mode == 0) {
                            o0 *= 0.08838834764831845f;
                            o1 *= 0.08838834764831845f;
                        }
                    }
                    __half* dst = ((mode == 0) ? g_Qh : (mode == 1) ? g_Kh : g_Vh) +
                                  ((size_t)(b * NHEADS + h) * S + s) * DK + d;
                    *reinterpret_cast<uint32_t*>(dst) = packh2(o0, o1);
                }
            }
        }
    }
}

// ---------------- Flash attention: Br=256, Bc=64, K/V fragment reuse x2 ------------
// Each warp owns 32 q-rows (two 16-row blocks); every K and V fragment feeds both
// blocks -> ldsm/mma ratio 0.31 vs 0.5, dropping crossbar demand below tensor time.
#define FSV 136
#define FQ_ROWS 256
#define Q_H (FQ_ROWS * FSV)
#define KV_H (64 * FSV)
#define FA_NSTG 3
#define FA_SMEM ((Q_H + FA_NSTG * 2 * KV_H) * 2)  // 174080

__global__ __launch_bounds__(256, 1) void fa_kernel(int S) {
    extern __shared__ __align__(16) unsigned char smraw[];
    uint32_t sm = (uint32_t)__cvta_generic_to_shared(smraw);

    const int bh = blockIdx.y;
    const int qtile = gridDim.x - 1 - blockIdx.x;  // longest-first
    const int qbase = qtile * FQ_ROWS;
    const __half* Qp = g_Qh + (size_t)bh * S * DK;
    const __half* Kp = g_Kh + (size_t)bh * S * DK;
    const __half* Vp = g_Vh + (size_t)bh * S * DK;

    const int tid = threadIdx.x, lane = tid & 31, wid = tid >> 5;
    const int lr = lane >> 2, lc = lane & 3;
    const int nkv = 4 * qtile + 4;

    const int a_row = (lane & 7) + ((lane >> 3) & 1) * 8;
    const int a_ch = (lane >> 4) * 8;
    const int kb_row = (lane >> 4) * 8 + (lane & 7);
    const int kb_k = ((lane >> 3) & 1) * 8;
    const int v_krow = (lane & 7) + ((lane >> 3) & 1) * 8;
    const int v_dch = (lane >> 4) * 8;

    auto kBase = [&](int stage) { return sm + (Q_H + stage * KV_H) * 2; };
    auto vBase = [&](int stage) { return sm + (Q_H + (FA_NSTG + stage) * KV_H) * 2; };

    // Q tile 256x128 -> smem (group 0)
#pragma unroll
    for (int i = 0; i < 16; i++) {
        int idx = tid + i * 256;
        int r = idx >> 4, c = (idx & 15) * 8;
        cp16(sm + (r * FSV + c) * 2, Qp + (size_t)(qbase + r) * DK + c);
    }
    cp_commit();

    auto prefetchKV = [&](int j) {
        int stage = j % 3;
        uint32_t kB = kBase(stage), vB = vBase(stage);
        const __half* Kt = Kp + (size_t)(j * 64) * DK;
        const __half* Vt = Vp + (size_t)(j * 64) * DK;
#pragma unroll
        for (int i = 0; i < 4; i++) {
            int idx = tid + i * 256;
            int r = idx >> 4, c = (idx & 15) * 8;
            cp16(kB + (r * FSV + c) * 2, Kt + (size_t)r * DK + c);
            cp16(vB + (r * FSV + c) * 2, Vt + (size_t)r * DK + c);
        }
    };

    prefetchKV(0);
    cp_commit();
    prefetchKV(1);
    cp_commit();

    CP_WAIT(1);  // Q + stage0 resident
    __syncthreads();

    float O0[16][4], O1[16][4];
#pragma unroll
    for (int i = 0; i < 16; i++)
#pragma unroll
        for (int j = 0; j < 4; j++) {
            O0[i][j] = 0.f;
            O1[i][j] = 0.f;
        }
    float m0 = -INFINITY, m1 = -INFINITY, m2 = -INFINITY, m3 = -INFINITY;
    float l0 = 0.f, l1 = 0.f, l2 = 0.f, l3 = 0.f;
    const int q0 = qbase + wid * 32 + lr;  // block0 base row; block1 = q0+16

    const int qrow0 = wid * 32 + a_row;       // block0 ldsm row
    const int qrow1 = wid * 32 + 16 + a_row;  // block1 ldsm row

    for (int j = 0; j < nkv; j++) {
        CP_WAIT(1);
        __syncthreads();
        if (j + 2 < nkv) prefetchKV(j + 2);
        cp_commit();

        const int stage = j % 3;
        const uint32_t kB = kBase(stage);
        const uint32_t vB = vBase(stage);
        const int kv0 = j * 64;

        // S = Q K^T for both row blocks (K fragments shared)
        float Sa0[8][4], Sa1[8][4];
#pragma unroll
        for (int i = 0; i < 8; i++)
#pragma unroll
            for (int t = 0; t < 4; t++) {
                Sa0[i][t] = 0.f;
                Sa1[i][t] = 0.f;
            }
#pragma unroll
        for (int kk = 0; kk < 8; kk++) {
            uint32_t a0[4], a1[4];
            ldsm4(a0, sm + (qrow0 * FSV + a_ch + kk * 16) * 2);
            ldsm4(a1, sm + (qrow1 * FSV + a_ch + kk * 16) * 2);
#pragma unroll
            for (int bt = 0; bt < 4; bt++) {
                uint32_t b[4];
                ldsm4(b, kB + ((bt * 16 + kb_row) * FSV + kb_k + kk * 16) * 2);
                mma16816(Sa0[2 * bt], a0, b[0], b[1]);
                mma16816(Sa0[2 * bt + 1], a0, b[2], b[3]);
                mma16816(Sa1[2 * bt], a1, b[0], b[1]);
                mma16816(Sa1[2 * bt + 1], a1, b[2], b[3]);
            }
        }

        // causal mask (last 4 kv tiles overlap the 256-row diagonal band)
        if (j >= nkv - 4) {
#pragma unroll
            for (int nt = 0; nt < 8; nt++) {
                int key = kv0 + nt * 8 + lc * 2;
                if (key > q0) Sa0[nt][0] = -INFINITY;
                if (key + 1 > q0) Sa0[nt][1] = -INFINITY;
                if (key > q0 + 8) Sa0[nt][2] = -INFINITY;
                if (key + 1 > q0 + 8) Sa0[nt][3] = -INFINITY;
                if (key > q0 + 16) Sa1[nt][0] = -INFINITY;
                if (key + 1 > q0 + 16) Sa1[nt][1] = -INFINITY;
                if (key > q0 + 24) Sa1[nt][2] = -INFINITY;
                if (key + 1 > q0 + 24) Sa1[nt][3] = -INFINITY;
            }
        }

        // online softmax (4 row-halves)
        float mx0 = -INFINITY, mx1 = -INFINITY, mx2 = -INFINITY, mx3 = -INFINITY;
#pragma unroll
        for (int nt = 0; nt < 8; nt++) {
            mx0 = fmaxf(mx0, fmaxf(Sa0[nt][0], Sa0[nt][1]));
            mx1 = fmaxf(mx1, fmaxf(Sa0[nt][2], Sa0[nt][3]));
            mx2 = fmaxf(mx2, fmaxf(Sa1[nt][0], Sa1[nt][1]));
            mx3 = fmaxf(mx3, fmaxf(Sa1[nt][2], Sa1[nt][3]));
        }
        mx0 = fmaxf(mx0, __shfl_xor_sync(0xffffffffu, mx0, 1));
        mx0 = fmaxf(mx0, __shfl_xor_sync(0xffffffffu, mx0, 2));
        mx1 = fmaxf(mx1, __shfl_xor_sync(0xffffffffu, mx1, 1));
        mx1 = fmaxf(mx1, __shfl_xor_sync(0xffffffffu, mx1, 2));
        mx2 = fmaxf(mx2, __shfl_xor_sync(0xffffffffu, mx2, 1));
        mx2 = fmaxf(mx2, __shfl_xor_sync(0xffffffffu, mx2, 2));
        mx3 = fmaxf(mx3, __shfl_xor_sync(0xffffffffu, mx3, 1));
        mx3 = fmaxf(mx3, __shfl_xor_sync(0xffffffffu, mx3, 2));
        float mn0 = fmaxf(m0, mx0), mn1 = fmaxf(m1, mx1);
        float mn2 = fmaxf(m2, mx2), mn3 = fmaxf(m3, mx3);
        float al0 = __expf(m0 - mn0), al1 = __expf(m1 - mn1);
        float al2 = __expf(m2 - mn2), al3 = __expf(m3 - mn3);
        m0 = mn0;
        m1 = mn1;
        m2 = mn2;
        m3 = mn3;
        float rs0 = 0.f, rs1 = 0.f, rs2 = 0.f, rs3 = 0.f;
#pragma unroll
        for (int nt = 0; nt < 8; nt++) {
            Sa0[nt][0] = __expf(Sa0[nt][0] - mn0);
            Sa0[nt][1] = __expf(Sa0[nt][1] - mn0);
            Sa0[nt][2] = __expf(Sa0[nt][2] - mn1);
            Sa0[nt][3] = __expf(Sa0[nt][3] - mn1);
            Sa1[nt][0] = __expf(Sa1[nt][0] - mn2);
            Sa1[nt][1] = __expf(Sa1[nt][1] - mn2);
            Sa1[nt][2] = __expf(Sa1[nt][2] - mn3);
            Sa1[nt][3] = __expf(Sa1[nt][3] - mn3);
            rs0 += Sa0[nt][0] + Sa0[nt][1];
            rs1 += Sa0[nt][2] + Sa0[nt][3];
            rs2 += Sa1[nt][0] + Sa1[nt][1];
            rs3 += Sa1[nt][2] + Sa1[nt][3];
        }
        rs0 += __shfl_xor_sync(0xffffffffu, rs0, 1);
        rs0 += __shfl_xor_sync(0xffffffffu, rs0, 2);
        rs1 += __shfl_xor_sync(0xffffffffu, rs1, 1);
        rs1 += __shfl_xor_sync(0xffffffffu, rs1, 2);
        rs2 += __shfl_xor_sync(0xffffffffu, rs2, 1);
        rs2 += __shfl_xor_sync(0xffffffffu, rs2, 2);
        rs3 += __shfl_xor_sync(0xffffffffu, rs3, 1);
        rs3 += __shfl_xor_sync(0xffffffffu, rs3, 2);
        l0 = l0 * al0 + rs0;
        l1 = l1 * al1 + rs1;
        l2 = l2 * al2 + rs2;
        l3 = l3 * al3 + rs3;
#pragma unroll
        for (int nt = 0; nt < 16; nt++) {
            O0[nt][0] *= al0;
            O0[nt][1] *= al0;
            O0[nt][2] *= al1;
            O0[nt][3] *= al1;
            O1[nt][0] *= al2;
            O1[nt][1] *= al2;
            O1[nt][2] *= al3;
            O1[nt][3] *= al3;
        }

        // O += P V for both row blocks (V fragments shared)
#pragma unroll
        for (int kt = 0; kt < 4; kt++) {
            uint32_t a0[4], a1[4];
            a0[0] = packh2(Sa0[2 * kt][0], Sa0[2 * kt][1]);
            a0[1] = packh2(Sa0[2 * kt][2], Sa0[2 * kt][3]);
            a0[2] = packh2(Sa0[2 * kt + 1][0], Sa0[2 * kt + 1][1]);
            a0[3] = packh2(Sa0[2 * kt + 1][2], Sa0[2 * kt + 1][3]);
            a1[0] = packh2(Sa1[2 * kt][0], Sa1[2 * kt][1]);
            a1[1] = packh2(Sa1[2 * kt][2], Sa1[2 * kt][3]);
            a1[2] = packh2(Sa1[2 * kt + 1][0], Sa1[2 * kt + 1][1]);
            a1[3] = packh2(Sa1[2 * kt + 1][2], Sa1[2 * kt + 1][3]);
#pragma unroll
            for (int bt = 0; bt < 8; bt++) {
                uint32_t b[4];
                ldsm4t(b, vB + ((kt * 16 + v_krow) * FSV + bt * 16 + v_dch) * 2);
                mma16816(O0[2 * bt], a0, b[0], b[1]);
                mma16816(O0[2 * bt + 1], a0, b[2], b[3]);
                mma16816(O1[2 * bt], a1, b[0], b[1]);
                mma16816(O1[2 * bt + 1], a1, b[2], b[3]);
            }
        }
    }

    // normalize + write fp16 to g_attnH [M, D_MODEL], columns h*128+d
    float il0 = 1.f / l0, il1 = 1.f / l1, il2 = 1.f / l2, il3 = 1.f / l3;
    const int hh = bh & (NHEADS - 1);
    const int bb = bh >> 4;
    __half* b00 = g_attnH + ((size_t)(bb * S + q0)) * D_MODEL + hh * DK;
    __half* b01 = b00 + (size_t)8 * D_MODEL;
    __half* b10 = b00 + (size_t)16 * D_MODEL;
    __half* b11 = b00 + (size_t)24 * D_MODEL;
#pragma unroll
    for (int nt = 0; nt < 16; nt++) {
        int d = nt * 8 + lc * 2;
        *reinterpret_cast<uint32_t*>(b00 + d) = packh2(O0[nt][0] * il0, O0[nt][1] * il0);
        *reinterpret_cast<uint32_t*>(b01 + d) = packh2(O0[nt][2] * il1, O0[nt][3] * il1);
        *reinterpret_cast<uint32_t*>(b10 + d) = packh2(O1[nt][0] * il2, O1[nt][1] * il2);
        *reinterpret_cast<uint32_t*>(b11 + d) = packh2(O1[nt][2] * il3, O1[nt][3] * il3);
    }
}

// ---------------- launch ----------------
extern "C" void kernel_launch(void* const* d_in, const int* in_sizes, int n_in,
                              void* d_out, int out_size) {
    const float* x = (const float*)d_in[0];
    const float* Wq = (const float*)d_in[1];
    const float* Wk = (const float*)d_in[2];
    const float* Wv = (const float*)d_in[3];
    const float* Wo = (const float*)d_in[4];
    const int* pos = (const int*)d_in[5];

    const int S = in_sizes[5];
    const int M = in_sizes[0] / D_MODEL;
    const int B = M / S;

    cudaFuncSetAttribute(gemm_f16_kernel, cudaFuncAttributeMaxDynamicSharedMemorySize, G_SMEM);
    cudaFuncSetAttribute(fa_kernel, cudaFuncAttributeMaxDynamicSharedMemorySize, FA_SMEM);

    rope_table_kernel<<<(S * (DK / 2) + 255) / 256, 256>>>(pos, S);
    convert_x_kernel<<<(M * D_MODEL / 4 + 255) / 256, 256>>>(x, M * D_MODEL);
    transpose_w_kernel<<<dim3(64, 64, 4), dim3(32, 8)>>>(Wq, Wk, Wv, Wo);

    gemm_f16_kernel<<<dim3(D_MODEL / 128, M / 128, 3), 256, G_SMEM>>>(nullptr, M, S, -1);

    fa_kernel<<<dim3(S / FQ_ROWS, B * NHEADS), 256, FA_SMEM>>>(S);

    gemm_f16_kernel<<<dim3(D_MODEL / 128, M / 128, 1), 256, G_SMEM>>>((float*)d_out, M, S, 3);
}

// round 12
// speedup vs baseline: 1.0147x; 1.0147x over previous
#include <cuda_runtime.h>
#include <cuda_fp16.h>
#include <cstdint>
#include <math.h>

#define D_MODEL 2048
#define NHEADS 16
#define DK 128
#define MAX_S 2048
#define MAX_M 4096
#define W_ELEMS ((size_t)D_MODEL * D_MODEL)

// ---------------- scratch (static device globals; no allocation) ----------------
__device__ __half g_Wt[4 * W_ELEMS];                 // [4][f][d] transposed fp16 weights (q,k,v,o)
__device__ __half g_xh[(size_t)MAX_M * D_MODEL];     // fp16 copy of x
__device__ __half g_Qh[(size_t)MAX_M * D_MODEL];     // [B,H,S,DK] (scale folded)
__device__ __half g_Kh[(size_t)MAX_M * D_MODEL];
__device__ __half g_Vh[(size_t)MAX_M * D_MODEL];
__device__ __half g_attnH[(size_t)MAX_M * D_MODEL];  // [M, D_MODEL]
__device__ float g_cosT[MAX_S * (DK / 2)];
__device__ float g_sinT[MAX_S * (DK / 2)];

// ---------------- asm helpers ----------------
__device__ __forceinline__ void ldsm4(uint32_t* r, uint32_t addr) {
    asm volatile("ldmatrix.sync.aligned.m8n8.x4.shared.b16 {%0,%1,%2,%3}, [%4];"
                 : "=r"(r[0]), "=r"(r[1]), "=r"(r[2]), "=r"(r[3]) : "r"(addr));
}
__device__ __forceinline__ void ldsm4t(uint32_t* r, uint32_t addr) {
    asm volatile("ldmatrix.sync.aligned.m8n8.x4.trans.shared.b16 {%0,%1,%2,%3}, [%4];"
                 : "=r"(r[0]), "=r"(r[1]), "=r"(r[2]), "=r"(r[3]) : "r"(addr));
}
__device__ __forceinline__ void mma16816(float* d, const uint32_t* a, uint32_t b0, uint32_t b1) {
    asm volatile(
        "mma.sync.aligned.m16n8k16.row.col.f32.f16.f16.f32 "
        "{%0,%1,%2,%3}, {%4,%5,%6,%7}, {%8,%9}, {%0,%1,%2,%3};"
        : "+f"(d[0]), "+f"(d[1]), "+f"(d[2]), "+f"(d[3])
        : "r"(a[0]), "r"(a[1]), "r"(a[2]), "r"(a[3]), "r"(b0), "r"(b1));
}
__device__ __forceinline__ void cp16(uint32_t saddr, const void* gptr) {
    asm volatile("cp.async.cg.shared.global [%0], [%1], 16;" :: "r"(saddr), "l"(gptr));
}
__device__ __forceinline__ void cp_commit() { asm volatile("cp.async.commit_group;"); }
#define CP_WAIT(N) asm volatile("cp.async.wait_group %0;" :: "n"(N))
__device__ __forceinline__ uint32_t packh2(float a, float b) {
    __half2 h = __floats2half2_rn(a, b);
    return *reinterpret_cast<uint32_t*>(&h);
}

// ---------------- RoPE table ----------------
__global__ void rope_table_kernel(const int* __restrict__ pos, int S) {
    int idx = blockIdx.x * blockDim.x + threadIdx.x;
    if (idx >= S * (DK / 2)) return;
    int s = idx / (DK / 2);
    int i = idx % (DK / 2);
    float invf = (float)pow(10000.0, -(double)(2 * i) / (double)DK);
    float ang = (float)pos[s] * invf;
    g_cosT[idx] = cosf(ang);
    g_sinT[idx] = sinf(ang);
}

// ---------------- converters ----------------
__global__ void convert_x_kernel(const float* __restrict__ x, int n) {
    int i = (blockIdx.x * blockDim.x + threadIdx.x) * 4;
    if (i >= n) return;
    float4 v = *reinterpret_cast<const float4*>(x + i);
    uint2 u = {packh2(v.x, v.y), packh2(v.z, v.w)};
    *reinterpret_cast<uint2*>(&g_xh[i]) = u;
}

__global__ void transpose_w_kernel(const float* __restrict__ Wq, const float* __restrict__ Wk,
                                   const float* __restrict__ Wv, const float* __restrict__ Wo) {
    __shared__ float t[32][33];
    const int z = blockIdx.z;
    const float* W = (z == 0) ? Wq : (z == 1) ? Wk : (z == 2) ? Wv : Wo;
    __half* dst = g_Wt + (size_t)z * W_ELEMS;
    int x0 = blockIdx.x * 32, y0 = blockIdx.y * 32;
    int tx = threadIdx.x, ty = threadIdx.y;
#pragma unroll
    for (int i = 0; i < 4; i++)
        t[ty + i * 8][tx] = W[(size_t)(y0 + ty + i * 8) * D_MODEL + x0 + tx];
    __syncthreads();
#pragma unroll
    for (int i = 0; i < 4; i++)
        dst[(size_t)(x0 + ty + i * 8) * D_MODEL + y0 + tx] = __float2half(t[tx][ty + i * 8]);
}

// ---------------- GEMM: 128x128 CTA tile, fp16 mma, 3-stage cp.async ----------------
#define SA 72                       // halves per smem row (64 data + 8 pad); 144B stride
#define G_STAGE_B (128 * SA * 2)    // bytes per matrix per stage (18432)
#define G_SMEM (3 * 2 * G_STAGE_B)  // 110592

__global__ __launch_bounds__(256, 2) void gemm_f16_kernel(float* __restrict__ outF, int M,
                                                          int S, int mode_in) {
    extern __shared__ __align__(16) unsigned char smraw[];
    uint32_t sm = (uint32_t)__cvta_generic_to_shared(smraw);

    const int mode = (mode_in < 0) ? (int)blockIdx.z : mode_in;
    const __half* Ag = (mode_in < 0) ? g_xh : g_attnH;
    const __half* Bg = g_Wt + (size_t)mode * W_ELEMS;  // [n][k] fp16
    const int bm = blockIdx.y * 128;
    const int bn = blockIdx.x * 128;
    const int tid = threadIdx.x;
    const int lane = tid & 31, wid = tid >> 5;
    const int wm = wid & 3, wn = wid >> 2;
    const int lr = lane >> 2, lc = lane & 3;

    const int a_row = (lane & 7) + ((lane >> 3) & 1) * 8;
    const int a_ch = (lane >> 4) * 8;
    const int aoff0 = ((wm * 32 + a_row) * SA + a_ch) * 2;
    const int aoff1 = ((wm * 32 + 16 + a_row) * SA + a_ch) * 2;
    const int b_row = (lane >> 4) * 8 + (lane & 7);
    const int b_k = ((lane >> 3) & 1) * 8;
    const int boff = ((wn * 64 + b_row) * SA + b_k) * 2;

    float acc[2][8][4];
#pragma unroll
    for (int i = 0; i < 2; i++)
#pragma unroll
        for (int j = 0; j < 8; j++)
#pragma unroll
            for (int k = 0; k < 4; k++) acc[i][j][k] = 0.f;

    auto prefetch = [&](int stage, int kt) {
        uint32_t aB = sm + stage * 2 * G_STAGE_B;
        uint32_t bB = aB + G_STAGE_B;
        const __half* Ap = Ag + (size_t)bm * D_MODEL + kt * 64;
        const __half* Bp = Bg + (size_t)bn * D_MODEL + kt * 64;
#pragma unroll
        for (int i = 0; i < 4; i++) {
            int idx = tid + i * 256;
            int r = idx >> 3, c = (idx & 7) * 8;
            cp16(aB + (r * SA + c) * 2, Ap + (size_t)r * D_MODEL + c);
            cp16(bB + (r * SA + c) * 2, Bp + (size_t)r * D_MODEL + c);
        }
    };

    prefetch(0, 0);
    cp_commit();
    prefetch(1, 1);
    cp_commit();

    for (int kt = 0; kt < 32; kt++) {
        CP_WAIT(1);
        __syncthreads();
        if (kt + 2 < 32) prefetch((kt + 2) % 3, kt + 2);
        cp_commit();

        uint32_t aB = sm + (kt % 3) * 2 * G_STAGE_B;
        uint32_t bB = aB + G_STAGE_B;

        uint32_t aF[4][2][4];
#pragma unroll
        for (int kk = 0; kk < 4; kk++) {
            ldsm4(aF[kk][0], aB + aoff0 + kk * 32);
            ldsm4(aF[kk][1], aB + aoff1 + kk * 32);
        }
#pragma unroll
        for (int kk = 0; kk < 4; kk++) {
#pragma unroll
            for (int bt = 0; bt < 4; bt++) {
                uint32_t b[4];
                ldsm4(b, bB + boff + bt * 16 * SA * 2 + kk * 32);
                mma16816(acc[0][2 * bt], aF[kk][0], b[0], b[1]);
                mma16816(acc[1][2 * bt], aF[kk][1], b[0], b[1]);
                mma16816(acc[0][2 * bt + 1], aF[kk][0], b[2], b[3]);
                mma16816(acc[1][2 * bt + 1], aF[kk][1], b[2], b[3]);
            }
        }
    }

#pragma unroll
    for (int mt = 0; mt < 2; mt++) {
#pragma unroll
        for (int nt = 0; nt < 8; nt++) {
#pragma unroll
            for (int half = 0; half < 2; half++) {
                int m = bm + wm * 32 + mt * 16 + lr + half * 8;
                int f = bn + wn * 64 + nt * 8 + lc * 2;
                float c0 = acc[mt][nt][half * 2];
                float c1 = acc[mt][nt][half * 2 + 1];
                if (mode == 3) {
                    *reinterpret_cast<float2*>(outF + (size_t)m * D_MODEL + f) =
                        make_float2(c0, c1);
                } else {
                    int b = m / S, s = m - b * S;
                    int h = f >> 7, d = f & (DK - 1);
                    float o0 = c0, o1 = c1;
                    if (mode < 2) {
                        int i = d >> 1;
                        float cs = g_cosT[s * (DK / 2) + i];
                        float sn = g_sinT[s * (DK / 2) + i];
                        o0 = c0 * cs - c1 * sn;
                        o1 = c0 * sn + c1 * cs;
                        if (mode == 0) {
                            o0 *= 0.08838834764831845f;
                            o1 *= 0.08838834764831845f;
                        }
                    }
                    __half* dst = ((mode == 0) ? g_Qh : (mode == 1) ? g_Kh : g_Vh) +
                                  ((size_t)(b * NHEADS + h) * S + s) * DK + d;
                    *reinterpret_cast<uint32_t*>(dst) = packh2(o0, o1);
                }
            }
        }
    }
}

// ---------------- Flash attention: Br=128, Bc=64, 2 CTAs/SM -----------------------
// 2-stage KV ring (104448 B smem) + no Qf preload -> fits 2 CTAs/SM at <=128 regs.
// Occupancy law (R3->R5): 4 warps/SMSP is the single biggest lever on this chip.
#define FSV 136
#define Q_H (128 * FSV)
#define KV_H (64 * FSV)
#define FA_SMEM ((Q_H + 4 * KV_H) * 2)  // 104448

__global__ __launch_bounds__(256, 2) void fa_kernel(int S) {
    extern __shared__ __align__(16) unsigned char smraw[];
    uint32_t sm = (uint32_t)__cvta_generic_to_shared(smraw);

    const int bh = blockIdx.y;
    const int qtile = gridDim.x - 1 - blockIdx.x;  // longest-first
    const int qbase = qtile * 128;
    const __half* Qp = g_Qh + (size_t)bh * S * DK;
    const __half* Kp = g_Kh + (size_t)bh * S * DK;
    const __half* Vp = g_Vh + (size_t)bh * S * DK;

    const int tid = threadIdx.x, lane = tid & 31, wid = tid >> 5;
    const int lr = lane >> 2, lc = lane & 3;
    const int nkv = 2 * qtile + 2;

    const int a_row = (lane & 7) + ((lane >> 3) & 1) * 8;
    const int a_ch = (lane >> 4) * 8;
    const int kb_row = (lane >> 4) * 8 + (lane & 7);
    const int kb_k = ((lane >> 3) & 1) * 8;
    const int v_krow = (lane & 7) + ((lane >> 3) & 1) * 8;
    const int v_dch = (lane >> 4) * 8;

    auto kBase = [&](int stage) { return sm + (Q_H + stage * KV_H) * 2; };
    auto vBase = [&](int stage) { return sm + (Q_H + (2 + stage) * KV_H) * 2; };

    // Q tile -> smem
#pragma unroll
    for (int i = 0; i < 8; i++) {
        int idx = tid + i * 256;
        int r = idx >> 4, c = (idx & 15) * 8;
        cp16(sm + (r * FSV + c) * 2, Qp + (size_t)(qbase + r) * DK + c);
    }

    auto prefetchKV = [&](int j) {
        int stage = j & 1;
        uint32_t kB = kBase(stage), vB = vBase(stage);
        const __half* Kt = Kp + (size_t)(j * 64) * DK;
        const __half* Vt = Vp + (size_t)(j * 64) * DK;
#pragma unroll
        for (int i = 0; i < 4; i++) {
            int idx = tid + i * 256;
            int r = idx >> 4, c = (idx & 15) * 8;
            cp16(kB + (r * FSV + c) * 2, Kt + (size_t)r * DK + c);
            cp16(vB + (r * FSV + c) * 2, Vt + (size_t)r * DK + c);
        }
    };

    prefetchKV(0);
    cp_commit();
    CP_WAIT(0);  // Q + stage0 resident
    __syncthreads();

    float O[16][4];
#pragma unroll
    for (int i = 0; i < 16; i++)
#pragma unroll
        for (int j = 0; j < 4; j++) O[i][j] = 0.f;
    float m0 = -INFINITY, m1 = -INFINITY, l0 = 0.f, l1 = 0.f;
    const int q0 = qbase + wid * 16 + lr;
    const int qrow = wid * 16 + a_row;

    for (int j = 0; j < nkv; j++) {
        if (j > 0) {
            CP_WAIT(0);
            __syncthreads();
        }
        if (j + 1 < nkv) {
            prefetchKV(j + 1);
            cp_commit();
        }

        const int stage = j & 1;
        const uint32_t kB = kBase(stage);
        const uint32_t vB = vBase(stage);
        const int kv0 = j * 64;

        // S = Q K^T  (Q re-read from smem each iter; saves 32 regs for occupancy)
        float Sa[8][4];
#pragma unroll
        for (int i = 0; i < 8; i++)
#pragma unroll
            for (int t = 0; t < 4; t++) Sa[i][t] = 0.f;
#pragma unroll
        for (int kk = 0; kk < 8; kk++) {
            uint32_t a[4];
            ldsm4(a, sm + (qrow * FSV + a_ch + kk * 16) * 2);
#pragma unroll
            for (int bt = 0; bt < 4; bt++) {
                uint32_t b[4];
                ldsm4(b, kB + ((bt * 16 + kb_row) * FSV + kb_k + kk * 16) * 2);
                mma16816(Sa[2 * bt], a, b[0], b[1]);
                mma16816(Sa[2 * bt + 1], a, b[2], b[3]);
            }
        }

        // causal mask (only last two kv tiles overlap the diagonal)
        if (j >= nkv - 2) {
#pragma unroll
            for (int nt = 0; nt < 8; nt++) {
                int key = kv0 + nt * 8 + lc * 2;
                if (key > q0) Sa[nt][0] = -INFINITY;
                if (key + 1 > q0) Sa[nt][1] = -INFINITY;
                if (key > q0 + 8) Sa[nt][2] = -INFINITY;
                if (key + 1 > q0 + 8) Sa[nt][3] = -INFINITY;
            }
        }

        // online softmax (fp32)
        float mx0 = -INFINITY, mx1 = -INFINITY;
#pragma unroll
        for (int nt = 0; nt < 8; nt++) {
            mx0 = fmaxf(mx0, fmaxf(Sa[nt][0], Sa[nt][1]));
            mx1 = fmaxf(mx1, fmaxf(Sa[nt][2], Sa[nt][3]));
        }
        mx0 = fmaxf(mx0, __shfl_xor_sync(0xffffffffu, mx0, 1));
        mx0 = fmaxf(mx0, __shfl_xor_sync(0xffffffffu, mx0, 2));
        mx1 = fmaxf(mx1, __shfl_xor_sync(0xffffffffu, mx1, 1));
        mx1 = fmaxf(mx1, __shfl_xor_sync(0xffffffffu, mx1, 2));
        float mn0 = fmaxf(m0, mx0), mn1 = fmaxf(m1, mx1);
        float al0 = __expf(m0 - mn0), al1 = __expf(m1 - mn1);
        m0 = mn0;
        m1 = mn1;
        float rs0 = 0.f, rs1 = 0.f;
#pragma unroll
        for (int nt = 0; nt < 8; nt++) {
            Sa[nt][0] = __expf(Sa[nt][0] - mn0);
            Sa[nt][1] = __expf(Sa[nt][1] - mn0);
            Sa[nt][2] = __expf(Sa[nt][2] - mn1);
            Sa[nt][3] = __expf(Sa[nt][3] - mn1);
            rs0 += Sa[nt][0] + Sa[nt][1];
            rs1 += Sa[nt][2] + Sa[nt][3];
        }
        rs0 += __shfl_xor_sync(0xffffffffu, rs0, 1);
        rs0 += __shfl_xor_sync(0xffffffffu, rs0, 2);
        rs1 += __shfl_xor_sync(0xffffffffu, rs1, 1);
        rs1 += __shfl_xor_sync(0xffffffffu, rs1, 2);
        l0 = l0 * al0 + rs0;
        l1 = l1 * al1 + rs1;
#pragma unroll
        for (int nt = 0; nt < 16; nt++) {
            O[nt][0] *= al0;
            O[nt][1] *= al0;
            O[nt][2] *= al1;
            O[nt][3] *= al1;
        }

        // O += P V  (P packed to fp16 A-fragments directly from registers)
#pragma unroll
        for (int kt = 0; kt < 4; kt++) {
            uint32_t a[4];
            a[0] = packh2(Sa[2 * kt][0], Sa[2 * kt][1]);
            a[1] = packh2(Sa[2 * kt][2], Sa[2 * kt][3]);
            a[2] = packh2(Sa[2 * kt + 1][0], Sa[2 * kt + 1][1]);
            a[3] = packh2(Sa[2 * kt + 1][2], Sa[2 * kt + 1][3]);
#pragma unroll
            for (int bt = 0; bt < 8; bt++) {
                uint32_t b[4];
                ldsm4t(b, vB + ((kt * 16 + v_krow) * FSV + bt * 16 + v_dch) * 2);
                mma16816(O[2 * bt], a, b[0], b[1]);
                mma16816(O[2 * bt + 1], a, b[2], b[3]);
            }
        }
    }

    // normalize + write fp16 to g_attnH [M, D_MODEL], columns h*128+d
    float il0 = 1.f / l0, il1 = 1.f / l1;
    const int hh = bh & (NHEADS - 1);
    const int bb = bh >> 4;
    __half* base0 = g_attnH + ((size_t)(bb * S + q0)) * D_MODEL + hh * DK;
    __half* base1 = base0 + (size_t)8 * D_MODEL;
#pragma unroll
    for (int nt = 0; nt < 16; nt++) {
        int d = nt * 8 + lc * 2;
        *reinterpret_cast<uint32_t*>(base0 + d) = packh2(O[nt][0] * il0, O[nt][1] * il0);
        *reinterpret_cast<uint32_t*>(base1 + d) = packh2(O[nt][2] * il1, O[nt][3] * il1);
    }
}

// ---------------- launch ----------------
extern "C" void kernel_launch(void* const* d_in, const int* in_sizes, int n_in,
                              void* d_out, int out_size) {
    const float* x = (const float*)d_in[0];
    const float* Wq = (const float*)d_in[1];
    const float* Wk = (const float*)d_in[2];
    const float* Wv = (const float*)d_in[3];
    const float* Wo = (const float*)d_in[4];
    const int* pos = (const int*)d_in[5];

    const int S = in_sizes[5];
    const int M = in_sizes[0] / D_MODEL;
    const int B = M / S;

    cudaFuncSetAttribute(gemm_f16_kernel, cudaFuncAttributeMaxDynamicSharedMemorySize, G_SMEM);
    cudaFuncSetAttribute(fa_kernel, cudaFuncAttributeMaxDynamicSharedMemorySize, FA_SMEM);

    rope_table_kernel<<<(S * (DK / 2) + 255) / 256, 256>>>(pos, S);
    convert_x_kernel<<<(M * D_MODEL / 4 + 255) / 256, 256>>>(x, M * D_MODEL);
    transpose_w_kernel<<<dim3(64, 64, 4), dim3(32, 8)>>>(Wq, Wk, Wv, Wo);

    gemm_f16_kernel<<<dim3(D_MODEL / 128, M / 128, 3), 256, G_SMEM>>>(nullptr, M, S, -1);

    fa_kernel<<<dim3(S / 128, B * NHEADS), 256, FA_SMEM>>>(S);

    gemm_f16_kernel<<<dim3(D_MODEL / 128, M / 128, 1), 256, G_SMEM>>>((float*)d_out, M, S, 3);
}

// round 13
// speedup vs baseline: 1.0160x; 1.0013x over previous
#include <cuda_runtime.h>
#include <cuda_fp16.h>
#include <cstdint>
#include <math.h>

#define D_MODEL 2048
#define NHEADS 16
#define DK 128
#define MAX_S 2048
#define MAX_M 4096
#define W_ELEMS ((size_t)D_MODEL * D_MODEL)

// ---------------- scratch (static device globals; no allocation) ----------------
__device__ __half g_Wt[4 * W_ELEMS];                 // [4][f][d] transposed fp16 weights (q,k,v,o)
__device__ __half g_xh[(size_t)MAX_M * D_MODEL];     // fp16 copy of x
__device__ __half g_Qh[(size_t)MAX_M * D_MODEL];     // [B,H,S,DK] (scale folded)
__device__ __half g_Kh[(size_t)MAX_M * D_MODEL];
__device__ __half g_Vh[(size_t)MAX_M * D_MODEL];
__device__ __half g_attnH[(size_t)MAX_M * D_MODEL];  // [M, D_MODEL]
__device__ float g_cosT[MAX_S * (DK / 2)];
__device__ float g_sinT[MAX_S * (DK / 2)];

// ---------------- asm helpers ----------------
__device__ __forceinline__ void ldsm4(uint32_t* r, uint32_t addr) {
    asm volatile("ldmatrix.sync.aligned.m8n8.x4.shared.b16 {%0,%1,%2,%3}, [%4];"
                 : "=r"(r[0]), "=r"(r[1]), "=r"(r[2]), "=r"(r[3]) : "r"(addr));
}
__device__ __forceinline__ void ldsm4t(uint32_t* r, uint32_t addr) {
    asm volatile("ldmatrix.sync.aligned.m8n8.x4.trans.shared.b16 {%0,%1,%2,%3}, [%4];"
                 : "=r"(r[0]), "=r"(r[1]), "=r"(r[2]), "=r"(r[3]) : "r"(addr));
}
__device__ __forceinline__ void mma16816(float* d, const uint32_t* a, uint32_t b0, uint32_t b1) {
    asm volatile(
        "mma.sync.aligned.m16n8k16.row.col.f32.f16.f16.f32 "
        "{%0,%1,%2,%3}, {%4,%5,%6,%7}, {%8,%9}, {%0,%1,%2,%3};"
        : "+f"(d[0]), "+f"(d[1]), "+f"(d[2]), "+f"(d[3])
        : "r"(a[0]), "r"(a[1]), "r"(a[2]), "r"(a[3]), "r"(b0), "r"(b1));
}
__device__ __forceinline__ void cp16(uint32_t saddr, const void* gptr) {
    asm volatile("cp.async.cg.shared.global [%0], [%1], 16;" :: "r"(saddr), "l"(gptr));
}
__device__ __forceinline__ void cp_commit() { asm volatile("cp.async.commit_group;"); }
#define CP_WAIT(N) asm volatile("cp.async.wait_group %0;" :: "n"(N))
__device__ __forceinline__ uint32_t packh2(float a, float b) {
    __half2 h = __floats2half2_rn(a, b);
    return *reinterpret_cast<uint32_t*>(&h);
}

// ---------------- RoPE table ----------------
__global__ void rope_table_kernel(const int* __restrict__ pos, int S) {
    int idx = blockIdx.x * blockDim.x + threadIdx.x;
    if (idx >= S * (DK / 2)) return;
    int s = idx / (DK / 2);
    int i = idx % (DK / 2);
    float invf = (float)pow(10000.0, -(double)(2 * i) / (double)DK);
    float ang = (float)pos[s] * invf;
    g_cosT[idx] = cosf(ang);
    g_sinT[idx] = sinf(ang);
}

// ---------------- converters ----------------
__global__ void convert_x_kernel(const float* __restrict__ x, int n) {
    int i = (blockIdx.x * blockDim.x + threadIdx.x) * 4;
    if (i >= n) return;
    float4 v = *reinterpret_cast<const float4*>(x + i);
    uint2 u = {packh2(v.x, v.y), packh2(v.z, v.w)};
    *reinterpret_cast<uint2*>(&g_xh[i]) = u;
}

__global__ void transpose_w_kernel(const float* __restrict__ Wq, const float* __restrict__ Wk,
                                   const float* __restrict__ Wv, const float* __restrict__ Wo) {
    __shared__ float t[32][33];
    const int z = blockIdx.z;
    const float* W = (z == 0) ? Wq : (z == 1) ? Wk : (z == 2) ? Wv : Wo;
    __half* dst = g_Wt + (size_t)z * W_ELEMS;
    int x0 = blockIdx.x * 32, y0 = blockIdx.y * 32;
    int tx = threadIdx.x, ty = threadIdx.y;
#pragma unroll
    for (int i = 0; i < 4; i++)
        t[ty + i * 8][tx] = W[(size_t)(y0 + ty + i * 8) * D_MODEL + x0 + tx];
    __syncthreads();
#pragma unroll
    for (int i = 0; i < 4; i++)
        dst[(size_t)(x0 + ty + i * 8) * D_MODEL + y0 + tx] = __float2half(t[tx][ty + i * 8]);
}

// ---------------- GEMM: 128x128 CTA tile, fp16 mma, 3-stage cp.async ----------------
#define SA 72                       // halves per smem row (64 data + 8 pad); 144B stride
#define G_STAGE_B (128 * SA * 2)    // bytes per matrix per stage (18432)
#define G_SMEM (3 * 2 * G_STAGE_B)  // 110592

__global__ __launch_bounds__(256, 2) void gemm_f16_kernel(float* __restrict__ outF, int M,
                                                          int S, int mode_in) {
    extern __shared__ __align__(16) unsigned char smraw[];
    uint32_t sm = (uint32_t)__cvta_generic_to_shared(smraw);

    const int mode = (mode_in < 0) ? (int)blockIdx.z : mode_in;
    const __half* Ag = (mode_in < 0) ? g_xh : g_attnH;
    const __half* Bg = g_Wt + (size_t)mode * W_ELEMS;  // [n][k] fp16
    const int bm = blockIdx.y * 128;
    const int bn = blockIdx.x * 128;
    const int tid = threadIdx.x;
    const int lane = tid & 31, wid = tid >> 5;
    const int wm = wid & 3, wn = wid >> 2;
    const int lr = lane >> 2, lc = lane & 3;

    const int a_row = (lane & 7) + ((lane >> 3) & 1) * 8;
    const int a_ch = (lane >> 4) * 8;
    const int aoff0 = ((wm * 32 + a_row) * SA + a_ch) * 2;
    const int aoff1 = ((wm * 32 + 16 + a_row) * SA + a_ch) * 2;
    const int b_row = (lane >> 4) * 8 + (lane & 7);
    const int b_k = ((lane >> 3) & 1) * 8;
    const int boff = ((wn * 64 + b_row) * SA + b_k) * 2;

    float acc[2][8][4];
#pragma unroll
    for (int i = 0; i < 2; i++)
#pragma unroll
        for (int j = 0; j < 8; j++)
#pragma unroll
            for (int k = 0; k < 4; k++) acc[i][j][k] = 0.f;

    auto prefetch = [&](int stage, int kt) {
        uint32_t aB = sm + stage * 2 * G_STAGE_B;
        uint32_t bB = aB + G_STAGE_B;
        const __half* Ap = Ag + (size_t)bm * D_MODEL + kt * 64;
        const __half* Bp = Bg + (size_t)bn * D_MODEL + kt * 64;
#pragma unroll
        for (int i = 0; i < 4; i++) {
            int idx = tid + i * 256;
            int r = idx >> 3, c = (idx & 7) * 8;
            cp16(aB + (r * SA + c) * 2, Ap + (size_t)r * D_MODEL + c);
            cp16(bB + (r * SA + c) * 2, Bp + (size_t)r * D_MODEL + c);
        }
    };

    prefetch(0, 0);
    cp_commit();
    prefetch(1, 1);
    cp_commit();

    for (int kt = 0; kt < 32; kt++) {
        CP_WAIT(1);
        __syncthreads();
        if (kt + 2 < 32) prefetch((kt + 2) % 3, kt + 2);
        cp_commit();

        uint32_t aB = sm + (kt % 3) * 2 * G_STAGE_B;
        uint32_t bB = aB + G_STAGE_B;

        uint32_t aF[4][2][4];
#pragma unroll
        for (int kk = 0; kk < 4; kk++) {
            ldsm4(aF[kk][0], aB + aoff0 + kk * 32);
            ldsm4(aF[kk][1], aB + aoff1 + kk * 32);
        }
#pragma unroll
        for (int kk = 0; kk < 4; kk++) {
#pragma unroll
            for (int bt = 0; bt < 4; bt++) {
                uint32_t b[4];
                ldsm4(b, bB + boff + bt * 16 * SA * 2 + kk * 32);
                mma16816(acc[0][2 * bt], aF[kk][0], b[0], b[1]);
                mma16816(acc[1][2 * bt], aF[kk][1], b[0], b[1]);
                mma16816(acc[0][2 * bt + 1], aF[kk][0], b[2], b[3]);
                mma16816(acc[1][2 * bt + 1], aF[kk][1], b[2], b[3]);
            }
        }
    }

#pragma unroll
    for (int mt = 0; mt < 2; mt++) {
#pragma unroll
        for (int nt = 0; nt < 8; nt++) {
#pragma unroll
            for (int half = 0; half < 2; half++) {
                int m = bm + wm * 32 + mt * 16 + lr + half * 8;
                int f = bn + wn * 64 + nt * 8 + lc * 2;
                float c0 = acc[mt][nt][half * 2];
                float c1 = acc[mt][nt][half * 2 + 1];
                if (mode == 3) {
                    *reinterpret_cast<float2*>(outF + (size_t)m * D_MODEL + f) =
                        make_float2(c0, c1);
                } else {
                    int b = m / S, s = m - b * S;
                    int h = f >> 7, d = f & (DK - 1);
                    float o0 = c0, o1 = c1;
                    if (mode < 2) {
                        int i = d >> 1;
                        float cs = g_cosT[s * (DK / 2) + i];
                        float sn = g_sinT[s * (DK / 2) + i];
                        o0 = c0 * cs - c1 * sn;
                        o1 = c0 * sn + c1 * cs;
                        if (mode == 0) {
                            o0 *= 0.08838834764831845f;
                            o1 *= 0.08838834764831845f;
                        }
                    }
                    __half* dst = ((mode == 0) ? g_Qh : (mode == 1) ? g_Kh : g_Vh) +
                                  ((size_t)(b * NHEADS + h) * S + s) * DK + d;
                    *reinterpret_cast<uint32_t*>(dst) = packh2(o0, o1);
                }
            }
        }
    }
}

// ---------------- Flash attention: Br=128, Bc=64, 2 CTAs/SM -----------------------
// 2-stage KV ring (104448 B smem) + no Qf preload -> fits 2 CTAs/SM at <=128 regs.
// Occupancy law (R3->R5): 4 warps/SMSP is the single biggest lever on this chip.
#define FSV 136
#define Q_H (128 * FSV)
#define KV_H (64 * FSV)
#define FA_SMEM ((Q_H + 4 * KV_H) * 2)  // 104448

__global__ __launch_bounds__(256, 2) void fa_kernel(int S) {
    extern __shared__ __align__(16) unsigned char smraw[];
    uint32_t sm = (uint32_t)__cvta_generic_to_shared(smraw);

    const int bh = blockIdx.y;
    const int qtile = gridDim.x - 1 - blockIdx.x;  // longest-first
    const int qbase = qtile * 128;
    const __half* Qp = g_Qh + (size_t)bh * S * DK;
    const __half* Kp = g_Kh + (size_t)bh * S * DK;
    const __half* Vp = g_Vh + (size_t)bh * S * DK;

    const int tid = threadIdx.x, lane = tid & 31, wid = tid >> 5;
    const int lr = lane >> 2, lc = lane & 3;
    const int nkv = 2 * qtile + 2;

    const int a_row = (lane & 7) + ((lane >> 3) & 1) * 8;
    const int a_ch = (lane >> 4) * 8;
    const int kb_row = (lane >> 4) * 8 + (lane & 7);
    const int kb_k = ((lane >> 3) & 1) * 8;
    const int v_krow = (lane & 7) + ((lane >> 3) & 1) * 8;
    const int v_dch = (lane >> 4) * 8;

    auto kBase = [&](int stage) { return sm + (Q_H + stage * KV_H) * 2; };
    auto vBase = [&](int stage) { return sm + (Q_H + (2 + stage) * KV_H) * 2; };

    // Q tile -> smem
#pragma unroll
    for (int i = 0; i < 8; i++) {
        int idx = tid + i * 256;
        int r = idx >> 4, c = (idx & 15) * 8;
        cp16(sm + (r * FSV + c) * 2, Qp + (size_t)(qbase + r) * DK + c);
    }

    auto prefetchKV = [&](int j) {
        int stage = j & 1;
        uint32_t kB = kBase(stage), vB = vBase(stage);
        const __half* Kt = Kp + (size_t)(j * 64) * DK;
        const __half* Vt = Vp + (size_t)(j * 64) * DK;
#pragma unroll
        for (int i = 0; i < 4; i++) {
            int idx = tid + i * 256;
            int r = idx >> 4, c = (idx & 15) * 8;
            cp16(kB + (r * FSV + c) * 2, Kt + (size_t)r * DK + c);
            cp16(vB + (r * FSV + c) * 2, Vt + (size_t)r * DK + c);
        }
    };

    prefetchKV(0);
    cp_commit();
    CP_WAIT(0);  // Q + stage0 resident
    __syncthreads();

    float O[16][4];
#pragma unroll
    for (int i = 0; i < 16; i++)
#pragma unroll
        for (int j = 0; j < 4; j++) O[i][j] = 0.f;
    float m0 = -INFINITY, m1 = -INFINITY, l0 = 0.f, l1 = 0.f;
    const int q0 = qbase + wid * 16 + lr;
    const int qrow = wid * 16 + a_row;

    for (int j = 0; j < nkv; j++) {
        if (j > 0) {
            CP_WAIT(0);
            __syncthreads();
        }
        if (j + 1 < nkv) {
            prefetchKV(j + 1);
            cp_commit();
        }

        const int stage = j & 1;
        const uint32_t kB = kBase(stage);
        const uint32_t vB = vBase(stage);
        const int kv0 = j * 64;

        // S = Q K^T  (Q re-read from smem each iter; saves 32 regs for occupancy)
        float Sa[8][4];
#pragma unroll
        for (int i = 0; i < 8; i++)
#pragma unroll
            for (int t = 0; t < 4; t++) Sa[i][t] = 0.f;
#pragma unroll
        for (int kk = 0; kk < 8; kk++) {
            uint32_t a[4];
            ldsm4(a, sm + (qrow * FSV + a_ch + kk * 16) * 2);
#pragma unroll
            for (int bt = 0; bt < 4; bt++) {
                uint32_t b[4];
                ldsm4(b, kB + ((bt * 16 + kb_row) * FSV + kb_k + kk * 16) * 2);
                mma16816(Sa[2 * bt], a, b[0], b[1]);
                mma16816(Sa[2 * bt + 1], a, b[2], b[3]);
            }
        }

        // causal mask (only last two kv tiles overlap the diagonal)
        if (j >= nkv - 2) {
#pragma unroll
            for (int nt = 0; nt < 8; nt++) {
                int key = kv0 + nt * 8 + lc * 2;
                if (key > q0) Sa[nt][0] = -INFINITY;
                if (key + 1 > q0) Sa[nt][1] = -INFINITY;
                if (key > q0 + 8) Sa[nt][2] = -INFINITY;
                if (key + 1 > q0 + 8) Sa[nt][3] = -INFINITY;
            }
        }

        // online softmax (fp32)
        float mx0 = -INFINITY, mx1 = -INFINITY;
#pragma unroll
        for (int nt = 0; nt < 8; nt++) {
            mx0 = fmaxf(mx0, fmaxf(Sa[nt][0], Sa[nt][1]));
            mx1 = fmaxf(mx1, fmaxf(Sa[nt][2], Sa[nt][3]));
        }
        mx0 = fmaxf(mx0, __shfl_xor_sync(0xffffffffu, mx0, 1));
        mx0 = fmaxf(mx0, __shfl_xor_sync(0xffffffffu, mx0, 2));
        mx1 = fmaxf(mx1, __shfl_xor_sync(0xffffffffu, mx1, 1));
        mx1 = fmaxf(mx1, __shfl_xor_sync(0xffffffffu, mx1, 2));
        float mn0 = fmaxf(m0, mx0), mn1 = fmaxf(m1, mx1);
        float al0 = __expf(m0 - mn0), al1 = __expf(m1 - mn1);
        m0 = mn0;
        m1 = mn1;
        float rs0 = 0.f, rs1 = 0.f;
#pragma unroll
        for (int nt = 0; nt < 8; nt++) {
            Sa[nt][0] = __expf(Sa[nt][0] - mn0);
            Sa[nt][1] = __expf(Sa[nt][1] - mn0);
            Sa[nt][2] = __expf(Sa[nt][2] - mn1);
            Sa[nt][3] = __expf(Sa[nt][3] - mn1);
            rs0 += Sa[nt][0] + Sa[nt][1];
            rs1 += Sa[nt][2] + Sa[nt][3];
        }
        rs0 += __shfl_xor_sync(0xffffffffu, rs0, 1);
        rs0 += __shfl_xor_sync(0xffffffffu, rs0, 2);
        rs1 += __shfl_xor_sync(0xffffffffu, rs1, 1);
        rs1 += __shfl_xor_sync(0xffffffffu, rs1, 2);
        l0 = l0 * al0 + rs0;
        l1 = l1 * al1 + rs1;
#pragma unroll
        for (int nt = 0; nt < 16; nt++) {
            O[nt][0] *= al0;
            O[nt][1] *= al0;
            O[nt][2] *= al1;
            O[nt][3] *= al1;
        }

        // O += P V  (P packed to fp16 A-fragments directly from registers)
#pragma unroll
        for (int kt = 0; kt < 4; kt++) {
            uint32_t a[4];
            a[0] = packh2(Sa[2 * kt][0], Sa[2 * kt][1]);
            a[1] = packh2(Sa[2 * kt][2], Sa[2 * kt][3]);
            a[2] = packh2(Sa[2 * kt + 1][0], Sa[2 * kt + 1][1]);
            a[3] = packh2(Sa[2 * kt + 1][2], Sa[2 * kt + 1][3]);
#pragma unroll
            for (int bt = 0; bt < 8; bt++) {
                uint32_t b[4];
                ldsm4t(b, vB + ((kt * 16 + v_krow) * FSV + bt * 16 + v_dch) * 2);
                mma16816(O[2 * bt], a, b[0], b[1]);
                mma16816(O[2 * bt + 1], a, b[2], b[3]);
            }
        }
    }

    // normalize + write fp16 to g_attnH [M, D_MODEL], columns h*128+d
    float il0 = 1.f / l0, il1 = 1.f / l1;
    const int hh = bh & (NHEADS - 1);
    const int bb = bh >> 4;
    __half* base0 = g_attnH + ((size_t)(bb * S + q0)) * D_MODEL + hh * DK;
    __half* base1 = base0 + (size_t)8 * D_MODEL;
#pragma unroll
    for (int nt = 0; nt < 16; nt++) {
        int d = nt * 8 + lc * 2;
        *reinterpret_cast<uint32_t*>(base0 + d) = packh2(O[nt][0] * il0, O[nt][1] * il0);
        *reinterpret_cast<uint32_t*>(base1 + d) = packh2(O[nt][2] * il1, O[nt][3] * il1);
    }
}

// ---------------- launch ----------------
extern "C" void kernel_launch(void* const* d_in, const int* in_sizes, int n_in,
                              void* d_out, int out_size) {
    const float* x = (const float*)d_in[0];
    const float* Wq = (const float*)d_in[1];
    const float* Wk = (const float*)d_in[2];
    const float* Wv = (const float*)d_in[3];
    const float* Wo = (const float*)d_in[4];
    const int* pos = (const int*)d_in[5];

    const int S = in_sizes[5];
    const int M = in_sizes[0] / D_MODEL;
    const int B = M / S;

    cudaFuncSetAttribute(gemm_f16_kernel, cudaFuncAttributeMaxDynamicSharedMemorySize, G_SMEM);
    cudaFuncSetAttribute(fa_kernel, cudaFuncAttributeMaxDynamicSharedMemorySize, FA_SMEM);

    rope_table_kernel<<<(S * (DK / 2) + 255) / 256, 256>>>(pos, S);
    convert_x_kernel<<<(M * D_MODEL / 4 + 255) / 256, 256>>>(x, M * D_MODEL);
    transpose_w_kernel<<<dim3(64, 64, 4), dim3(32, 8)>>>(Wq, Wk, Wv, Wo);

    gemm_f16_kernel<<<dim3(D_MODEL / 128, M / 128, 3), 256, G_SMEM>>>(nullptr, M, S, -1);

    fa_kernel<<<dim3(S / 128, B * NHEADS), 256, FA_SMEM>>>(S);

    gemm_f16_kernel<<<dim3(D_MODEL / 128, M / 128, 1), 256, G_SMEM>>>((float*)d_out, M, S, 3);
}

// round 14
// speedup vs baseline: 1.0206x; 1.0046x over previous
#include <cuda_runtime.h>
#include <cuda_fp16.h>
#include <cstdint>
#include <math.h>

#define D_MODEL 2048
#define NHEADS 16
#define DK 128
#define MAX_S 2048
#define MAX_M 4096
#define W_ELEMS ((size_t)D_MODEL * D_MODEL)

// ---------------- scratch (static device globals; no allocation) ----------------
__device__ __half g_Wt[4 * W_ELEMS];                 // [4][f][d] transposed fp16 weights (q,k,v,o)
__device__ __half g_xh[(size_t)MAX_M * D_MODEL];     // fp16 copy of x
__device__ __half g_Qh[(size_t)MAX_M * D_MODEL];     // [B,H,S,DK] (scale folded)
__device__ __half g_Kh[(size_t)MAX_M * D_MODEL];
__device__ __half g_Vh[(size_t)MAX_M * D_MODEL];
__device__ __half g_attnH[(size_t)MAX_M * D_MODEL];  // [M, D_MODEL]
__device__ float g_cosT[MAX_S * (DK / 2)];
__device__ float g_sinT[MAX_S * (DK / 2)];

// ---------------- asm helpers ----------------
__device__ __forceinline__ void ldsm4(uint32_t* r, uint32_t addr) {
    asm volatile("ldmatrix.sync.aligned.m8n8.x4.shared.b16 {%0,%1,%2,%3}, [%4];"
                 : "=r"(r[0]), "=r"(r[1]), "=r"(r[2]), "=r"(r[3]) : "r"(addr));
}
__device__ __forceinline__ void ldsm4t(uint32_t* r, uint32_t addr) {
    asm volatile("ldmatrix.sync.aligned.m8n8.x4.trans.shared.b16 {%0,%1,%2,%3}, [%4];"
                 : "=r"(r[0]), "=r"(r[1]), "=r"(r[2]), "=r"(r[3]) : "r"(addr));
}
__device__ __forceinline__ void mma16816(float* d, const uint32_t* a, uint32_t b0, uint32_t b1) {
    asm volatile(
        "mma.sync.aligned.m16n8k16.row.col.f32.f16.f16.f32 "
        "{%0,%1,%2,%3}, {%4,%5,%6,%7}, {%8,%9}, {%0,%1,%2,%3};"
        : "+f"(d[0]), "+f"(d[1]), "+f"(d[2]), "+f"(d[3])
        : "r"(a[0]), "r"(a[1]), "r"(a[2]), "r"(a[3]), "r"(b0), "r"(b1));
}
__device__ __forceinline__ void cp16(uint32_t saddr, const void* gptr) {
    asm volatile("cp.async.cg.shared.global [%0], [%1], 16;" :: "r"(saddr), "l"(gptr));
}
__device__ __forceinline__ void cp_commit() { asm volatile("cp.async.commit_group;"); }
#define CP_WAIT(N) asm volatile("cp.async.wait_group %0;" :: "n"(N))
__device__ __forceinline__ uint32_t packh2(float a, float b) {
    __half2 h = __floats2half2_rn(a, b);
    return *reinterpret_cast<uint32_t*>(&h);
}

// ---------------- RoPE table ----------------
__global__ void rope_table_kernel(const int* __restrict__ pos, int S) {
    int idx = blockIdx.x * blockDim.x + threadIdx.x;
    if (idx >= S * (DK / 2)) return;
    int s = idx / (DK / 2);
    int i = idx % (DK / 2);
    float invf = (float)pow(10000.0, -(double)(2 * i) / (double)DK);
    float ang = (float)pos[s] * invf;
    g_cosT[idx] = cosf(ang);
    g_sinT[idx] = sinf(ang);
}

// ---------------- converters ----------------
__global__ void convert_x_kernel(const float* __restrict__ x, int n) {
    int i = (blockIdx.x * blockDim.x + threadIdx.x) * 4;
    if (i >= n) return;
    float4 v = *reinterpret_cast<const float4*>(x + i);
    uint2 u = {packh2(v.x, v.y), packh2(v.z, v.w)};
    *reinterpret_cast<uint2*>(&g_xh[i]) = u;
}

__global__ void transpose_w_kernel(const float* __restrict__ Wq, const float* __restrict__ Wk,
                                   const float* __restrict__ Wv, const float* __restrict__ Wo) {
    __shared__ float t[32][33];
    const int z = blockIdx.z;
    const float* W = (z == 0) ? Wq : (z == 1) ? Wk : (z == 2) ? Wv : Wo;
    __half* dst = g_Wt + (size_t)z * W_ELEMS;
    int x0 = blockIdx.x * 32, y0 = blockIdx.y * 32;
    int tx = threadIdx.x, ty = threadIdx.y;
#pragma unroll
    for (int i = 0; i < 4; i++)
        t[ty + i * 8][tx] = W[(size_t)(y0 + ty + i * 8) * D_MODEL + x0 + tx];
    __syncthreads();
#pragma unroll
    for (int i = 0; i < 4; i++)
        dst[(size_t)(x0 + ty + i * 8) * D_MODEL + y0 + tx] = __float2half(t[tx][ty + i * 8]);
}

// ---------------- GEMM: 128x128 CTA tile, fp16 mma, 3-stage cp.async ----------------
#define SA 72                       // halves per smem row (64 data + 8 pad); 144B stride
#define G_STAGE_B (128 * SA * 2)    // bytes per matrix per stage (18432)
#define G_SMEM (3 * 2 * G_STAGE_B)  // 110592

__global__ __launch_bounds__(256, 2) void gemm_f16_kernel(float* __restrict__ outF, int M,
                                                          int S, int mode_in) {
    extern __shared__ __align__(16) unsigned char smraw[];
    uint32_t sm = (uint32_t)__cvta_generic_to_shared(smraw);

    const int mode = (mode_in < 0) ? (int)blockIdx.z : mode_in;
    const __half* Ag = (mode_in < 0) ? g_xh : g_attnH;
    const __half* Bg = g_Wt + (size_t)mode * W_ELEMS;  // [n][k] fp16
    const int bm = blockIdx.y * 128;
    const int bn = blockIdx.x * 128;
    const int tid = threadIdx.x;
    const int lane = tid & 31, wid = tid >> 5;
    const int wm = wid & 3, wn = wid >> 2;
    const int lr = lane >> 2, lc = lane & 3;

    const int a_row = (lane & 7) + ((lane >> 3) & 1) * 8;
    const int a_ch = (lane >> 4) * 8;
    const int aoff0 = ((wm * 32 + a_row) * SA + a_ch) * 2;
    const int aoff1 = ((wm * 32 + 16 + a_row) * SA + a_ch) * 2;
    const int b_row = (lane >> 4) * 8 + (lane & 7);
    const int b_k = ((lane >> 3) & 1) * 8;
    const int boff = ((wn * 64 + b_row) * SA + b_k) * 2;

    float acc[2][8][4];
#pragma unroll
    for (int i = 0; i < 2; i++)
#pragma unroll
        for (int j = 0; j < 8; j++)
#pragma unroll
            for (int k = 0; k < 4; k++) acc[i][j][k] = 0.f;

    auto prefetch = [&](int stage, int kt) {
        uint32_t aB = sm + stage * 2 * G_STAGE_B;
        uint32_t bB = aB + G_STAGE_B;
        const __half* Ap = Ag + (size_t)bm * D_MODEL + kt * 64;
        const __half* Bp = Bg + (size_t)bn * D_MODEL + kt * 64;
#pragma unroll
        for (int i = 0; i < 4; i++) {
            int idx = tid + i * 256;
            int r = idx >> 3, c = (idx & 7) * 8;
            cp16(aB + (r * SA + c) * 2, Ap + (size_t)r * D_MODEL + c);
            cp16(bB + (r * SA + c) * 2, Bp + (size_t)r * D_MODEL + c);
        }
    };

    prefetch(0, 0);
    cp_commit();
    prefetch(1, 1);
    cp_commit();

    for (int kt = 0; kt < 32; kt++) {
        CP_WAIT(1);
        __syncthreads();
        if (kt + 2 < 32) prefetch((kt + 2) % 3, kt + 2);
        cp_commit();

        uint32_t aB = sm + (kt % 3) * 2 * G_STAGE_B;
        uint32_t bB = aB + G_STAGE_B;

        uint32_t aF[4][2][4];
#pragma unroll
        for (int kk = 0; kk < 4; kk++) {
            ldsm4(aF[kk][0], aB + aoff0 + kk * 32);
            ldsm4(aF[kk][1], aB + aoff1 + kk * 32);
        }
#pragma unroll
        for (int kk = 0; kk < 4; kk++) {
#pragma unroll
            for (int bt = 0; bt < 4; bt++) {
                uint32_t b[4];
                ldsm4(b, bB + boff + bt * 16 * SA * 2 + kk * 32);
                mma16816(acc[0][2 * bt], aF[kk][0], b[0], b[1]);
                mma16816(acc[1][2 * bt], aF[kk][1], b[0], b[1]);
                mma16816(acc[0][2 * bt + 1], aF[kk][0], b[2], b[3]);
                mma16816(acc[1][2 * bt + 1], aF[kk][1], b[2], b[3]);
            }
        }
    }

#pragma unroll
    for (int mt = 0; mt < 2; mt++) {
#pragma unroll
        for (int nt = 0; nt < 8; nt++) {
#pragma unroll
            for (int half = 0; half < 2; half++) {
                int m = bm + wm * 32 + mt * 16 + lr + half * 8;
                int f = bn + wn * 64 + nt * 8 + lc * 2;
                float c0 = acc[mt][nt][half * 2];
                float c1 = acc[mt][nt][half * 2 + 1];
                if (mode == 3) {
                    *reinterpret_cast<float2*>(outF + (size_t)m * D_MODEL + f) =
                        make_float2(c0, c1);
                } else {
                    int b = m / S, s = m - b * S;
                    int h = f >> 7, d = f & (DK - 1);
                    float o0 = c0, o1 = c1;
                    if (mode < 2) {
                        int i = d >> 1;
                        float cs = g_cosT[s * (DK / 2) + i];
                        float sn = g_sinT[s * (DK / 2) + i];
                        o0 = c0 * cs - c1 * sn;
                        o1 = c0 * sn + c1 * cs;
                        if (mode == 0) {
                            o0 *= 0.08838834764831845f;
                            o1 *= 0.08838834764831845f;
                        }
                    }
                    __half* dst = ((mode == 0) ? g_Qh : (mode == 1) ? g_Kh : g_Vh) +
                                  ((size_t)(b * NHEADS + h) * S + s) * DK + d;
                    *reinterpret_cast<uint32_t*>(dst) = packh2(o0, o1);
                }
            }
        }
    }
}

// ---------------- Flash attention: Br=128, Bc=64, 2 CTAs/SM -----------------------
// 2-stage KV ring (104448 B smem) + no Qf preload -> fits 2 CTAs/SM at <=128 regs.
// Occupancy law (R3->R5): 4 warps/SMSP is the single biggest lever on this chip.
#define FSV 136
#define Q_H (128 * FSV)
#define KV_H (64 * FSV)
#define FA_SMEM ((Q_H + 4 * KV_H) * 2)  // 104448

__global__ __launch_bounds__(256, 2) void fa_kernel(int S) {
    extern __shared__ __align__(16) unsigned char smraw[];
    uint32_t sm = (uint32_t)__cvta_generic_to_shared(smraw);

    const int bh = blockIdx.y;
    const int qtile = gridDim.x - 1 - blockIdx.x;  // longest-first
    const int qbase = qtile * 128;
    const __half* Qp = g_Qh + (size_t)bh * S * DK;
    const __half* Kp = g_Kh + (size_t)bh * S * DK;
    const __half* Vp = g_Vh + (size_t)bh * S * DK;

    const int tid = threadIdx.x, lane = tid & 31, wid = tid >> 5;
    const int lr = lane >> 2, lc = lane & 3;
    const int nkv = 2 * qtile + 2;

    const int a_row = (lane & 7) + ((lane >> 3) & 1) * 8;
    const int a_ch = (lane >> 4) * 8;
    const int kb_row = (lane >> 4) * 8 + (lane & 7);
    const int kb_k = ((lane >> 3) & 1) * 8;
    const int v_krow = (lane & 7) + ((lane >> 3) & 1) * 8;
    const int v_dch = (lane >> 4) * 8;

    auto kBase = [&](int stage) { return sm + (Q_H + stage * KV_H) * 2; };
    auto vBase = [&](int stage) { return sm + (Q_H + (2 + stage) * KV_H) * 2; };

    // Q tile -> smem
#pragma unroll
    for (int i = 0; i < 8; i++) {
        int idx = tid + i * 256;
        int r = idx >> 4, c = (idx & 15) * 8;
        cp16(sm + (r * FSV + c) * 2, Qp + (size_t)(qbase + r) * DK + c);
    }

    auto prefetchKV = [&](int j) {
        int stage = j & 1;
        uint32_t kB = kBase(stage), vB = vBase(stage);
        const __half* Kt = Kp + (size_t)(j * 64) * DK;
        const __half* Vt = Vp + (size_t)(j * 64) * DK;
#pragma unroll
        for (int i = 0; i < 4; i++) {
            int idx = tid + i * 256;
            int r = idx >> 4, c = (idx & 15) * 8;
            cp16(kB + (r * FSV + c) * 2, Kt + (size_t)r * DK + c);
            cp16(vB + (r * FSV + c) * 2, Vt + (size_t)r * DK + c);
        }
    };

    prefetchKV(0);
    cp_commit();
    CP_WAIT(0);  // Q + stage0 resident
    __syncthreads();

    float O[16][4];
#pragma unroll
    for (int i = 0; i < 16; i++)
#pragma unroll
        for (int j = 0; j < 4; j++) O[i][j] = 0.f;
    float m0 = -INFINITY, m1 = -INFINITY, l0 = 0.f, l1 = 0.f;
    const int q0 = qbase + wid * 16 + lr;
    const int qrow = wid * 16 + a_row;

    for (int j = 0; j < nkv; j++) {
        if (j > 0) {
            CP_WAIT(0);
            __syncthreads();
        }
        if (j + 1 < nkv) {
            prefetchKV(j + 1);
            cp_commit();
        }

        const int stage = j & 1;
        const uint32_t kB = kBase(stage);
        const uint32_t vB = vBase(stage);
        const int kv0 = j * 64;

        // S = Q K^T  (Q re-read from smem each iter; saves 32 regs for occupancy)
        float Sa[8][4];
#pragma unroll
        for (int i = 0; i < 8; i++)
#pragma unroll
            for (int t = 0; t < 4; t++) Sa[i][t] = 0.f;
#pragma unroll
        for (int kk = 0; kk < 8; kk++) {
            uint32_t a[4];
            ldsm4(a, sm + (qrow * FSV + a_ch + kk * 16) * 2);
#pragma unroll
            for (int bt = 0; bt < 4; bt++) {
                uint32_t b[4];
                ldsm4(b, kB + ((bt * 16 + kb_row) * FSV + kb_k + kk * 16) * 2);
                mma16816(Sa[2 * bt], a, b[0], b[1]);
                mma16816(Sa[2 * bt + 1], a, b[2], b[3]);
            }
        }

        // causal mask (only last two kv tiles overlap the diagonal)
        if (j >= nkv - 2) {
#pragma unroll
            for (int nt = 0; nt < 8; nt++) {
                int key = kv0 + nt * 8 + lc * 2;
                if (key > q0) Sa[nt][0] = -INFINITY;
                if (key + 1 > q0) Sa[nt][1] = -INFINITY;
                if (key > q0 + 8) Sa[nt][2] = -INFINITY;
                if (key + 1 > q0 + 8) Sa[nt][3] = -INFINITY;
            }
        }

        // online softmax (fp32)
        float mx0 = -INFINITY, mx1 = -INFINITY;
#pragma unroll
        for (int nt = 0; nt < 8; nt++) {
            mx0 = fmaxf(mx0, fmaxf(Sa[nt][0], Sa[nt][1]));
            mx1 = fmaxf(mx1, fmaxf(Sa[nt][2], Sa[nt][3]));
        }
        mx0 = fmaxf(mx0, __shfl_xor_sync(0xffffffffu, mx0, 1));
        mx0 = fmaxf(mx0, __shfl_xor_sync(0xffffffffu, mx0, 2));
        mx1 = fmaxf(mx1, __shfl_xor_sync(0xffffffffu, mx1, 1));
        mx1 = fmaxf(mx1, __shfl_xor_sync(0xffffffffu, mx1, 2));
        float mn0 = fmaxf(m0, mx0), mn1 = fmaxf(m1, mx1);
        float al0 = __expf(m0 - mn0), al1 = __expf(m1 - mn1);
        m0 = mn0;
        m1 = mn1;
        float rs0 = 0.f, rs1 = 0.f;
#pragma unroll
        for (int nt = 0; nt < 8; nt++) {
            Sa[nt][0] = __expf(Sa[nt][0] - mn0);
            Sa[nt][1] = __expf(Sa[nt][1] - mn0);
            Sa[nt][2] = __expf(Sa[nt][2] - mn1);
            Sa[nt][3] = __expf(Sa[nt][3] - mn1);
            rs0 += Sa[nt][0] + Sa[nt][1];
            rs1 += Sa[nt][2] + Sa[nt][3];
        }
        rs0 += __shfl_xor_sync(0xffffffffu, rs0, 1);
        rs0 += __shfl_xor_sync(0xffffffffu, rs0, 2);
        rs1 += __shfl_xor_sync(0xffffffffu, rs1, 1);
        rs1 += __shfl_xor_sync(0xffffffffu, rs1, 2);
        l0 = l0 * al0 + rs0;
        l1 = l1 * al1 + rs1;
#pragma unroll
        for (int nt = 0; nt < 16; nt++) {
            O[nt][0] *= al0;
            O[nt][1] *= al0;
            O[nt][2] *= al1;
            O[nt][3] *= al1;
        }

        // O += P V  (P packed to fp16 A-fragments directly from registers)
#pragma unroll
        for (int kt = 0; kt < 4; kt++) {
            uint32_t a[4];
            a[0] = packh2(Sa[2 * kt][0], Sa[2 * kt][1]);
            a[1] = packh2(Sa[2 * kt][2], Sa[2 * kt][3]);
            a[2] = packh2(Sa[2 * kt + 1][0], Sa[2 * kt + 1][1]);
            a[3] = packh2(Sa[2 * kt + 1][2], Sa[2 * kt + 1][3]);
#pragma unroll
            for (int bt = 0; bt < 8; bt++) {
                uint32_t b[4];
                ldsm4t(b, vB + ((kt * 16 + v_krow) * FSV + bt * 16 + v_dch) * 2);
                mma16816(O[2 * bt], a, b[0], b[1]);
                mma16816(O[2 * bt + 1], a, b[2], b[3]);
            }
        }
    }

    // normalize + write fp16 to g_attnH [M, D_MODEL], columns h*128+d
    float il0 = 1.f / l0, il1 = 1.f / l1;
    const int hh = bh & (NHEADS - 1);
    const int bb = bh >> 4;
    __half* base0 = g_attnH + ((size_t)(bb * S + q0)) * D_MODEL + hh * DK;
    __half* base1 = base0 + (size_t)8 * D_MODEL;
#pragma unroll
    for (int nt = 0; nt < 16; nt++) {
        int d = nt * 8 + lc * 2;
        *reinterpret_cast<uint32_t*>(base0 + d) = packh2(O[nt][0] * il0, O[nt][1] * il0);
        *reinterpret_cast<uint32_t*>(base1 + d) = packh2(O[nt][2] * il1, O[nt][3] * il1);
    }
}

// ---------------- launch ----------------
extern "C" void kernel_launch(void* const* d_in, const int* in_sizes, int n_in,
                              void* d_out, int out_size) {
    const float* x = (const float*)d_in[0];
    const float* Wq = (const float*)d_in[1];
    const float* Wk = (const float*)d_in[2];
    const float* Wv = (const float*)d_in[3];
    const float* Wo = (const float*)d_in[4];
    const int* pos = (const int*)d_in[5];

    const int S = in_sizes[5];
    const int M = in_sizes[0] / D_MODEL;
    const int B = M / S;

    cudaFuncSetAttribute(gemm_f16_kernel, cudaFuncAttributeMaxDynamicSharedMemorySize, G_SMEM);
    cudaFuncSetAttribute(fa_kernel, cudaFuncAttributeMaxDynamicSharedMemorySize, FA_SMEM);

    rope_table_kernel<<<(S * (DK / 2) + 255) / 256, 256>>>(pos, S);
    convert_x_kernel<<<(M * D_MODEL / 4 + 255) / 256, 256>>>(x, M * D_MODEL);
    transpose_w_kernel<<<dim3(64, 64, 4), dim3(32, 8)>>>(Wq, Wk, Wv, Wo);

    gemm_f16_kernel<<<dim3(D_MODEL / 128, M / 128, 3), 256, G_SMEM>>>(nullptr, M, S, -1);

    fa_kernel<<<dim3(S / 128, B * NHEADS), 256, FA_SMEM>>>(S);

    gemm_f16_kernel<<<dim3(D_MODEL / 128, M / 128, 1), 256, G_SMEM>>>((float*)d_out, M, S, 3);
}